// round 16
// baseline (speedup 1.0000x reference)
#include <cuda_runtime.h>
#include <cuda_bf16.h>
#include <math.h>
#include <stdint.h>

#define BATCH 8
#define DIMC  256
#define HH    48
#define WWD   48
#define HW    2304
#define HEADS 8
#define DH    32
#define HKD   24
#define NKS   576
#define ATTN_SCALE 0.17677669529663687f
#define ATTN_SCALE_LOG2E 0.25501633617699413f   // ATTN_SCALE / ln(2)

// ==================== scratch (device globals) ====================
__device__ float g_q   [BATCH * DIMC * HW];
__device__ float g_kvT [64 * HW * DH];
__device__ __nv_bfloat16 g_kvshi[BATCH * NKS * DIMC];
__device__ __nv_bfloat16 g_kvslo[BATCH * NKS * DIMC];
__device__ __nv_bfloat16 g_kthi[64 * NKS * DH];
__device__ __nv_bfloat16 g_ktlo[64 * NKS * DH];
__device__ __nv_bfloat16 g_vhi [64 * DH * NKS];
__device__ __nv_bfloat16 g_vlo [64 * DH * NKS];
__device__ __nv_bfloat16 g_wqhi[DIMC * DIMC], g_wqlo[DIMC * DIMC];
__device__ __nv_bfloat16 g_wohi[DIMC * DIMC], g_wolo[DIMC * DIMC];
__device__ __nv_bfloat16 g_wkhi[DIMC * DIMC], g_wklo[DIMC * DIMC];
__device__ __nv_bfloat16 g_wvhi[DIMC * DIMC], g_wvlo[DIMC * DIMC];
__device__ __nv_bfloat16 g_xthi[BATCH * HW * DIMC], g_xtlo[BATCH * HW * DIMC];
__device__ __nv_bfloat16 g_aothi[BATCH * HW * DIMC], g_aotlo[BATCH * HW * DIMC];

// ==================== helpers ====================
__device__ __forceinline__ float warp_sum(float v) {
#pragma unroll
    for (int o = 16; o; o >>= 1) v += __shfl_xor_sync(0xffffffffu, v, o);
    return v;
}
__device__ __forceinline__ uint32_t smem_u32(const void* p) {
    uint32_t a;
    asm("{ .reg .u64 t; cvta.to.shared.u64 t, %1; cvt.u32.u64 %0, t; }" : "=r"(a) : "l"(p));
    return a;
}
__device__ __forceinline__ uint32_t pack_bf16(float a, float b) {
    uint32_t r;
    asm("cvt.rn.satfinite.bf16x2.f32 %0, %1, %2;" : "=r"(r) : "f"(b), "f"(a));
    return r;
}
__device__ __forceinline__ float ex2f(float x) {
    float r;
    asm("ex2.approx.f32 %0, %1;" : "=f"(r) : "f"(x));
    return r;
}
__device__ __forceinline__ void mma16816(float* d, const uint32_t* a, const uint32_t* b,
                                         const float* c) {
    asm volatile("mma.sync.aligned.m16n8k16.row.col.f32.bf16.bf16.f32 "
        "{%0,%1,%2,%3}, {%4,%5,%6,%7}, {%8,%9}, {%10,%11,%12,%13};"
        : "=f"(d[0]), "=f"(d[1]), "=f"(d[2]), "=f"(d[3])
        : "r"(a[0]), "r"(a[1]), "r"(a[2]), "r"(a[3]),
          "r"(b[0]), "r"(b[1]),
          "f"(c[0]), "f"(c[1]), "f"(c[2]), "f"(c[3]));
}
__device__ __forceinline__ void ldsm_x4(uint32_t& r0, uint32_t& r1, uint32_t& r2,
                                        uint32_t& r3, uint32_t addr) {
    asm volatile("ldmatrix.sync.aligned.m8n8.x4.shared.b16 {%0,%1,%2,%3}, [%4];"
                 : "=r"(r0), "=r"(r1), "=r"(r2), "=r"(r3) : "r"(addr));
}
__device__ __forceinline__ void ldsm_x2(uint32_t& r0, uint32_t& r1, uint32_t addr) {
    asm volatile("ldmatrix.sync.aligned.m8n8.x2.shared.b16 {%0,%1}, [%2];"
                 : "=r"(r0), "=r"(r1) : "r"(addr));
}
__device__ __forceinline__ void cp16(uint32_t saddr, const void* g) {
    asm volatile("cp.async.cg.shared.global [%0], [%1], 16;" :: "r"(saddr), "l"(g));
}
#define CP_COMMIT() asm volatile("cp.async.commit_group;" ::: "memory")
#define CP_WAIT2()  asm volatile("cp.async.wait_group 2;" ::: "memory")
#define CP_WAIT1()  asm volatile("cp.async.wait_group 1;" ::: "memory")
#define CP_WAIT0()  asm volatile("cp.async.wait_group 0;" ::: "memory")

// ==================== fused preprocessing ====================
__global__ void preproc_kernel(const float* __restrict__ wq, const float* __restrict__ wo,
                               const float* __restrict__ wk, const float* __restrict__ wv,
                               const float* __restrict__ x,  const float* __restrict__ kv,
                               __nv_bfloat16* __restrict__ wqhi, __nv_bfloat16* __restrict__ wqlo,
                               __nv_bfloat16* __restrict__ wohi, __nv_bfloat16* __restrict__ wolo,
                               __nv_bfloat16* __restrict__ wkhi, __nv_bfloat16* __restrict__ wklo,
                               __nv_bfloat16* __restrict__ wvhi, __nv_bfloat16* __restrict__ wvlo,
                               __nv_bfloat16* __restrict__ xthi, __nv_bfloat16* __restrict__ xtlo,
                               float* __restrict__ kvT)
{
    __shared__ float tile[32][33];
    const int blk = blockIdx.x;
    const int tid = threadIdx.x;

    if (blk < 1024) {
        int i = blk * 256 + tid;
        int which = i >> 16, j = i & 65535;
        const float* src = (which == 0) ? wq : (which == 1) ? wo : (which == 2) ? wk : wv;
        __nv_bfloat16* dhi = (which == 0) ? wqhi : (which == 1) ? wohi : (which == 2) ? wkhi : wvhi;
        __nv_bfloat16* dlo = (which == 0) ? wqlo : (which == 1) ? wolo : (which == 2) ? wklo : wvlo;
        float v = src[j];
        __nv_bfloat16 hi = __float2bfloat16(v);
        dhi[j] = hi;
        dlo[j] = __float2bfloat16(v - __bfloat162float(hi));
    } else if (blk < 5632) {
        int j = blk - 1024;
        int n0 = (j % 72) * 32, c0 = ((j / 72) & 7) * 32, b = j / 576;
        for (int i = tid; i < 1024; i += 256) {
            int c = i >> 5, n = i & 31;
            tile[c][n] = x[((size_t)b * DIMC + c0 + c) * HW + n0 + n];
        }
        __syncthreads();
        for (int i = tid; i < 1024; i += 256) {
            int n = i >> 5, c = i & 31;
            float v = tile[c][n];
            __nv_bfloat16 hi = __float2bfloat16(v);
            size_t idx = ((size_t)b * HW + n0 + n) * DIMC + c0 + c;
            xthi[idx] = hi;
            xtlo[idx] = __float2bfloat16(v - __bfloat162float(hi));
        }
    } else {
        int j = blk - 5632;
        int n0 = (j % 72) * 32, h = (j / 72) & 7, b = j / 576;
        for (int i = tid; i < 1024; i += 256) {
            int c = i >> 5, n = i & 31;
            tile[c][n] = kv[((size_t)b * DIMC + h * DH + c) * HW + n0 + n];
        }
        __syncthreads();
        for (int i = tid; i < 1024; i += 256) {
            int n = i >> 5, c = i & 31;
            kvT[(((size_t)(b * 8 + h)) * HW + n0 + n) * DH + c] = tile[c][n];
        }
    }
}

// ==================== TC mainloop (3-stage pipeline, per-ks B frags) ====================
#define G_BUF  30720
#define G_SMEM (3 * G_BUF)

__device__ __forceinline__ void tc_mainloop(
    uint32_t sb, int tid, int lane, int warp,
    const uint32_t* __restrict__ whi, const uint32_t* __restrict__ wlo, int m0,
    const uint32_t* __restrict__ xh,  const uint32_t* __restrict__ xl,  int n0,
    float acc[2][4][4])
{
    auto prefetch = [&](int kc, int buf) {
        const uint32_t bb = sb + buf * G_BUF;
#pragma unroll
        for (int s = tid; s < 1536; s += 256) {
            if (s < 512) {
                int row = s >> 2, p = s & 3;
                cp16(bb + row * 80 + p * 16, whi + (size_t)(m0 + row) * 128 + kc * 16 + p * 4);
            } else if (s < 1024) {
                int t = s - 512, row = t >> 2, p = t & 3;
                cp16(bb + 10240 + row * 80 + p * 16, wlo + (size_t)(m0 + row) * 128 + kc * 16 + p * 4);
            } else if (s < 1280) {
                int t = s - 1024, row = t >> 2, p = t & 3;
                cp16(bb + 20480 + row * 80 + p * 16, xh + (size_t)(n0 + row) * 128 + kc * 16 + p * 4);
            } else {
                int t = s - 1280, row = t >> 2, p = t & 3;
                cp16(bb + 25600 + row * 80 + p * 16, xl + (size_t)(n0 + row) * 128 + kc * 16 + p * 4);
            }
        }
        CP_COMMIT();
    };

    prefetch(0, 0);
    prefetch(1, 1);

    const int warp_m = warp >> 1, warp_n = warp & 1;
    const int m_base = warp_m * 32, n_base = warp_n * 32;
    const uint32_t a_laneoff  = (uint32_t)((lane & 15) * 80 + (lane >> 4) * 16);
    const uint32_t b2_laneoff = (uint32_t)((lane & 7) * 80 + ((lane >> 3) & 1) * 16);

    int buf = 0;
    for (int kc = 0; kc < 8; ++kc) {
        if (kc < 6)       { prefetch(kc + 2, (kc + 2) % 3); CP_WAIT2(); }
        else if (kc == 6) { CP_WAIT1(); }
        else              { CP_WAIT0(); }
        __syncthreads();
        const uint32_t bb = sb + buf * G_BUF;
        buf = (buf + 1) % 3;

#pragma unroll
        for (int ks = 0; ks < 2; ++ks) {
            uint32_t bfh[4][2], bfl[4][2];
#pragma unroll
            for (int nf = 0; nf < 4; ++nf) {
                uint32_t ad = bb + 20480u + (uint32_t)(n_base + nf * 8) * 80u +
                              b2_laneoff + (uint32_t)ks * 32u;
                ldsm_x2(bfh[nf][0], bfh[nf][1], ad);
                ldsm_x2(bfl[nf][0], bfl[nf][1], ad + 5120u);
            }
#pragma unroll
            for (int mf = 0; mf < 2; ++mf) {
                uint32_t ad = bb + (uint32_t)(m_base + mf * 16) * 80u + a_laneoff + (uint32_t)ks * 32u;
                uint32_t ah[4], al[4];
                ldsm_x4(ah[0], ah[1], ah[2], ah[3], ad);
                ldsm_x4(al[0], al[1], al[2], al[3], ad + 10240u);
#pragma unroll
                for (int nf = 0; nf < 4; ++nf) {
                    mma16816(acc[mf][nf], ah, bfh[nf], acc[mf][nf]);
                    mma16816(acc[mf][nf], ah, bfl[nf], acc[mf][nf]);
                    mma16816(acc[mf][nf], al, bfh[nf], acc[mf][nf]);
                }
            }
        }
        __syncthreads();
    }
}

// ---- q / o projection ----
__global__ void __launch_bounds__(256, 3)
gemm_tc_kernel(const uint32_t* __restrict__ whi, const uint32_t* __restrict__ wlo,
               const float* __restrict__ bias,
               const uint32_t* __restrict__ xthi, const uint32_t* __restrict__ xtlo,
               float* __restrict__ C)
{
    extern __shared__ char smem[];
    const uint32_t sb = smem_u32(smem);
    const int tid = threadIdx.x, lane = tid & 31, warp = tid >> 5;
    const int n0 = blockIdx.x * 64;
    const int m0 = blockIdx.y * 128;
    const int b  = blockIdx.z;

    float acc[2][4][4] = {};
    tc_mainloop(sb, tid, lane, warp, whi, wlo, m0,
                xthi + (size_t)b * HW * 128, xtlo + (size_t)b * HW * 128, n0, acc);

    const int warp_m = warp >> 1, warp_n = warp & 1;
    const int m_base = warp_m * 32, n_base = warp_n * 32;
    const int r = lane >> 2, c2 = lane & 3;
    float* Cb = C + (size_t)b * DIMC * HW;
#pragma unroll
    for (int mf = 0; mf < 2; ++mf) {
        int mrow = m0 + m_base + mf * 16;
        float b0 = bias[mrow + r], b1 = bias[mrow + r + 8];
#pragma unroll
        for (int nf = 0; nf < 4; ++nf) {
            int n = n0 + n_base + nf * 8 + c2 * 2;
            *(float2*)(Cb + (size_t)(mrow + r) * HW + n) =
                make_float2(acc[mf][nf][0] + b0, acc[mf][nf][1] + b0);
            *(float2*)(Cb + (size_t)(mrow + r + 8) * HW + n) =
                make_float2(acc[mf][nf][2] + b1, acc[mf][nf][3] + b1);
        }
    }
}

// ---- k / v projection ----
__global__ void __launch_bounds__(256, 3)
gemm_kv_tc_kernel(const uint32_t* __restrict__ wkhi, const uint32_t* __restrict__ wklo,
                  const uint32_t* __restrict__ wvhi, const uint32_t* __restrict__ wvlo,
                  const float* __restrict__ bk, const float* __restrict__ bv,
                  const uint32_t* __restrict__ kvshi, const uint32_t* __restrict__ kvslo,
                  __nv_bfloat16* __restrict__ kthi, __nv_bfloat16* __restrict__ ktlo,
                  uint32_t* __restrict__ vhi, uint32_t* __restrict__ vlo)
{
    extern __shared__ char smem[];
    const uint32_t sb = smem_u32(smem);
    const int tid = threadIdx.x, lane = tid & 31, warp = tid >> 5;
    const int n0 = blockIdx.x * 64;
    const bool isV = blockIdx.y >= 2;
    const int m0 = (blockIdx.y & 1) * 128;
    const int b  = blockIdx.z;
    const uint32_t* whi = isV ? wvhi : wkhi;
    const uint32_t* wlo = isV ? wvlo : wklo;
    const float* bias = isV ? bv : bk;

    float acc[2][4][4] = {};
    tc_mainloop(sb, tid, lane, warp, whi, wlo, m0,
                kvshi + (size_t)b * NKS * 128, kvslo + (size_t)b * NKS * 128, n0, acc);

    const int warp_m = warp >> 1, warp_n = warp & 1;
    const int m_base = warp_m * 32, n_base = warp_n * 32;
    const int r = lane >> 2, c2 = lane & 3;

#pragma unroll
    for (int mf = 0; mf < 2; ++mf) {
        const int mrow = m0 + m_base + mf * 16 + r;
        const int bh = b * 8 + (mrow >> 5);
        const int dh = mrow & 31;
        const float b0 = bias[mrow], b1 = bias[mrow + 8];
#pragma unroll
        for (int nf = 0; nf < 4; ++nf) {
            const int n = n0 + n_base + nf * 8 + c2 * 2;
            float a0 = acc[mf][nf][0] + b0, a1 = acc[mf][nf][1] + b0;
            float a2 = acc[mf][nf][2] + b1, a3 = acc[mf][nf][3] + b1;
            float h0 = __bfloat162float(__float2bfloat16(a0));
            float h1 = __bfloat162float(__float2bfloat16(a1));
            float h2 = __bfloat162float(__float2bfloat16(a2));
            float h3 = __bfloat162float(__float2bfloat16(a3));
            if (!isV) {
                __nv_bfloat16* oh = kthi + (size_t)bh * NKS * DH;
                __nv_bfloat16* ol = ktlo + (size_t)bh * NKS * DH;
                oh[(size_t)n * DH + dh]           = __float2bfloat16(h0);
                oh[(size_t)(n + 1) * DH + dh]     = __float2bfloat16(h1);
                oh[(size_t)n * DH + dh + 8]       = __float2bfloat16(h2);
                oh[(size_t)(n + 1) * DH + dh + 8] = __float2bfloat16(h3);
                ol[(size_t)n * DH + dh]           = __float2bfloat16(a0 - h0);
                ol[(size_t)(n + 1) * DH + dh]     = __float2bfloat16(a1 - h1);
                ol[(size_t)n * DH + dh + 8]       = __float2bfloat16(a2 - h2);
                ol[(size_t)(n + 1) * DH + dh + 8] = __float2bfloat16(a3 - h3);
            } else {
                uint32_t* oh = vhi + (size_t)bh * DH * (NKS / 2);
                uint32_t* ol = vlo + (size_t)bh * DH * (NKS / 2);
                oh[(size_t)dh * (NKS / 2) + n / 2]       = pack_bf16(h0, h1);
                oh[(size_t)(dh + 8) * (NKS / 2) + n / 2] = pack_bf16(h2, h3);
                ol[(size_t)dh * (NKS / 2) + n / 2]       = pack_bf16(a0 - h0, a1 - h1);
                ol[(size_t)(dh + 8) * (NKS / 2) + n / 2] = pack_bf16(a2 - h2, a3 - h3);
            }
        }
    }
}

// ==================== offset + sample -> split bf16 [pos][ch] ====================
#define OS_SMEM (528 * 33 * 4)

__global__ void __launch_bounds__(256)
offset_sample_kernel(const float* __restrict__ q,
                     const float* __restrict__ kvT,
                     const float* __restrict__ w_dw,
                     const float* __restrict__ b_dw,
                     const float* __restrict__ ln_w,
                     const float* __restrict__ ln_b,
                     const float* __restrict__ w_off,
                     __nv_bfloat16* __restrict__ kvshi,
                     __nv_bfloat16* __restrict__ kvslo)
{
    extern __shared__ float sp[];
    __shared__ float s_wdw[32 * 25];
    __shared__ float s_bdw[32], s_lnw[32], s_lnb[32], s_woff[64];

    const int tid = threadIdx.x;
    const int bh = blockIdx.y, b = bh >> 3, h = bh & 7;
    const int hk0 = blockIdx.x * 4;
    const int y0 = 2 * hk0 - 2;

    for (int i = tid; i < 800; i += 256) s_wdw[i] = w_dw[i];
    if (tid < 32) { s_bdw[tid] = b_dw[tid]; s_lnw[tid] = ln_w[tid]; s_lnb[tid] = ln_b[tid]; }
    if (tid < 64) s_woff[tid] = w_off[tid];

    const float* qh = q + (size_t)(b * DIMC + h * DH) * HW;
    for (int i = tid; i < 16896; i += 256) {
        int dh = i / 528, p = i - dh * 528;
        int y = y0 + p / 48, x = p - (p / 48) * 48;
        float v = 0.f;
        if ((unsigned)y < (unsigned)HH)
            v = qh[(size_t)dh * HW + y * WWD + x];
        sp[p * 33 + dh] = v;
    }
    __syncthreads();

    const int lane = tid & 31, warp = tid >> 5;
    const float* kvb = kvT + (size_t)bh * HW * DH;
    __nv_bfloat16* outh = kvshi + ((size_t)b * NKS) * DIMC + h * DH;
    __nv_bfloat16* outl = kvslo + ((size_t)b * NKS) * DIMC + h * DH;

#pragma unroll
    for (int s = 0; s < 12; ++s) {
        const int p = s * 8 + warp;
        const int hk = hk0 + p / 24;
        const int wk = p - (p / 24) * 24;
        const int pos = hk * HKD + wk;

        const int dy = 2 * (hk - hk0);
        float t = 0.f;
#pragma unroll
        for (int i = 0; i < 5; ++i) {
            const int rb = (dy + i) * 48;
#pragma unroll
            for (int j = 0; j < 5; ++j) {
                int xx = wk * 2 - 2 + j;
                if ((unsigned)xx < (unsigned)WWD)
                    t += sp[(rb + xx) * 33 + lane] * s_wdw[lane * 25 + i * 5 + j];
            }
        }
        t += s_bdw[lane];

        float mu  = warp_sum(t) * (1.f / 32.f);
        float d   = t - mu;
        float var = warp_sum(d * d) * (1.f / 32.f);
        t = d * rsqrtf(var + 1e-5f) * s_lnw[lane] + s_lnb[lane];
        t = 0.5f * t * (1.f + erff(t * 0.70710678118654752f));

        float o0 = warp_sum(s_woff[lane] * t);
        float o1 = warp_sum(s_woff[32 + lane] * t);

        const float refy = (0.5f + (float)hk) * (2.f / 23.f) - 1.f;
        const float refx = (0.5f + (float)wk) * (2.f / 23.f) - 1.f;
        float py = fminf(fmaxf(o0 + refy, -1.f), 1.f);
        float px = fminf(fmaxf(o1 + refx, -1.f), 1.f);

        float gx = (px + 1.f) * 0.5f * 47.f;
        float gy = (py + 1.f) * 0.5f * 47.f;
        float fx = floorf(gx), fy = floorf(gy);
        float wx = gx - fx,   wy = gy - fy;
        int x0i = min(max((int)fx, 0), 47);
        int x1i = min(max((int)fx + 1, 0), 47);
        int y0i = min(max((int)fy, 0), 47);
        int y1i = min(max((int)fy + 1, 0), 47);

        float v00 = kvb[(size_t)(y0i * WWD + x0i) * DH + lane];
        float v01 = kvb[(size_t)(y0i * WWD + x1i) * DH + lane];
        float v10 = kvb[(size_t)(y1i * WWD + x0i) * DH + lane];
        float v11 = kvb[(size_t)(y1i * WWD + x1i) * DH + lane];

        float val = (1.f - wx) * (1.f - wy) * v00 + wx * (1.f - wy) * v01 +
                    (1.f - wx) * wy * v10 + wx * wy * v11;

        __nv_bfloat16 hi = __float2bfloat16(val);
        outh[(size_t)pos * DIMC + lane] = hi;
        outl[(size_t)pos * DIMC + lane] = __float2bfloat16(val - __bfloat162float(hi));
    }
}

// ==================== streamed mma.sync attention (rowsum via ones-MMA) ====================
#define BUF_SZ  19456
#define A_SMEM  (2 * BUF_SZ)

__global__ void __launch_bounds__(256, 4)
attn_mma_kernel(const float* __restrict__ q,
                const uint32_t* __restrict__ kthi, const uint32_t* __restrict__ ktlo,
                const uint32_t* __restrict__ vhi,  const uint32_t* __restrict__ vlo,
                uint32_t* __restrict__ aothi, uint32_t* __restrict__ aotlo)
{
    extern __shared__ char smem[];
    const uint32_t sb = smem_u32(smem);
    __nv_bfloat16* sqh = (__nv_bfloat16*)(smem + BUF_SZ);
    __nv_bfloat16* sql = (__nv_bfloat16*)(smem + BUF_SZ + 9216);

    const int tid  = threadIdx.x;
    const int lane = tid & 31, warp = tid >> 5;
    const int bh = blockIdx.y, b = bh >> 3, h = bh & 7;
    const int m0 = blockIdx.x * 128;

    const uint32_t* gkh = kthi + (size_t)bh * 9216;
    const uint32_t* gkl = ktlo + (size_t)bh * 9216;
    const uint32_t* gvh = vhi + (size_t)bh * 9216;
    const uint32_t* gvl = vlo + (size_t)bh * 9216;

    auto prefetch = [&](int c, int buf) {
        const uint32_t bb = sb + buf * BUF_SZ;
#pragma unroll
        for (int s = tid; s < 1024; s += 256) {
            if (s < 256) {
                int n = s >> 2, p = s & 3;
                cp16(bb + n * 80 + p * 16, gkh + c * 1024 + s * 4);
            } else if (s < 512) {
                int t = s - 256, n = t >> 2, p = t & 3;
                cp16(bb + 5120 + n * 80 + p * 16, gkl + c * 1024 + t * 4);
            } else if (s < 768) {
                int t = s - 512, dh = t >> 3, p = t & 7;
                cp16(bb + 10240 + dh * 144 + p * 16, gvh + dh * 288 + c * 32 + p * 4);
            } else {
                int t = s - 768, dh = t >> 3, p = t & 7;
                cp16(bb + 14848 + dh * 144 + p * 16, gvl + dh * 288 + c * 32 + p * 4);
            }
        }
        CP_COMMIT();
    };

    prefetch(0, 0);

    const float* qb = q + (size_t)(b * DIMC + h * DH) * HW + m0;
    for (int i = tid; i < 4096; i += 256) {
        int dh = i >> 7, m = i & 127;
        float x = qb[(size_t)dh * HW + m] * ATTN_SCALE_LOG2E;
        __nv_bfloat16 hi = __float2bfloat16(x);
        float lo = x - __bfloat162float(hi);
        sqh[m * 36 + dh] = hi;
        sql[m * 36 + dh] = __float2bfloat16(lo);
    }
    __syncthreads();

    const int r = lane >> 2, c2 = lane & 3;
    const int mrow = warp * 16;
    uint32_t qfh[2][4], qfl[2][4];
#pragma unroll
    for (int ks = 0; ks < 2; ++ks) {
        int k0 = ks * 16 + c2 * 2;
        qfh[ks][0] = *(const uint32_t*)(sqh + (mrow + r) * 36 + k0);
        qfh[ks][1] = *(const uint32_t*)(sqh + (mrow + r + 8) * 36 + k0);
        qfh[ks][2] = *(const uint32_t*)(sqh + (mrow + r) * 36 + k0 + 8);
        qfh[ks][3] = *(const uint32_t*)(sqh + (mrow + r + 8) * 36 + k0 + 8);
        qfl[ks][0] = *(const uint32_t*)(sql + (mrow + r) * 36 + k0);
        qfl[ks][1] = *(const uint32_t*)(sql + (mrow + r + 8) * 36 + k0);
        qfl[ks][2] = *(const uint32_t*)(sql + (mrow + r) * 36 + k0 + 8);
        qfl[ks][3] = *(const uint32_t*)(sql + (mrow + r + 8) * 36 + k0 + 8);
    }
    __syncthreads();

    const uint32_t k_laneoff = ((uint32_t)(lane & 7) * 20u + (uint32_t)(lane >> 3) * 4u) * 4u;
    const uint32_t v_laneoff = ((uint32_t)(lane & 7) * 36u + (uint32_t)((lane >> 3) & 1) * 4u) * 4u;
    const uint32_t v_hl = (lane < 16) ? 10240u : 14848u;

    // all-ones bf16 B fragment: every element 1.0 -> each D column = row sum of A
    uint32_t onesfrag[2] = { 0x3F803F80u, 0x3F803F80u };

    float O[4][4] = {};
    float Ors[4] = {};   // rowsum accumulator: Ors[0] = rs(row r), Ors[2] = rs(row r+8)

    for (int chunk = 0; chunk < 9; ++chunk) {
        if (chunk < 8) { prefetch(chunk + 1, (chunk + 1) & 1); CP_WAIT1(); }
        else           { CP_WAIT0(); }
        __syncthreads();

        const uint32_t bufb = sb + (chunk & 1) * BUF_SZ;
        float S[8][4];
#pragma unroll
        for (int nb = 0; nb < 8; ++nb)
#pragma unroll
            for (int i = 0; i < 4; ++i) S[nb][i] = 0.f;

#pragma unroll
        for (int nb = 0; nb < 8; ++nb) {
            uint32_t h0, h1, h2, h3, l0, l1, l2, l3;
            ldsm_x4(h0, h1, h2, h3, bufb + k_laneoff + (uint32_t)nb * 640u);
            ldsm_x4(l0, l1, l2, l3, bufb + 5120u + k_laneoff + (uint32_t)nb * 640u);
            uint32_t bh0[2] = {h0, h1}, bh1[2] = {h2, h3};
            uint32_t bl0[2] = {l0, l1}, bl1[2] = {l2, l3};
            mma16816(S[nb], qfh[0], bh0, S[nb]);
            mma16816(S[nb], qfh[1], bh1, S[nb]);
            mma16816(S[nb], qfh[0], bl0, S[nb]);
            mma16816(S[nb], qfh[1], bl1, S[nb]);
            mma16816(S[nb], qfl[0], bh0, S[nb]);
            mma16816(S[nb], qfl[1], bh1, S[nb]);
        }

#pragma unroll
        for (int j = 0; j < 4; ++j) {
            float e[8];
#pragma unroll
            for (int i = 0; i < 4; ++i) {
                e[i]     = ex2f(S[2 * j][i]);
                e[4 + i] = ex2f(S[2 * j + 1][i]);
            }

            uint32_t ph[4], pl[4];
#pragma unroll
            for (int i = 0; i < 4; ++i) {
                float a = e[2 * i], bb2 = e[2 * i + 1];
                uint32_t hp = pack_bf16(a, bb2);
                float ra = a   - __uint_as_float(hp << 16);
                float rb = bb2 - __uint_as_float(hp & 0xffff0000u);
                ph[i] = hp;
                pl[i] = pack_bf16(ra, rb);
            }

            // rowsum via tensor pipe (replaces 8 scalar adds + final shfl reduce)
            mma16816(Ors, ph, onesfrag, Ors);
            mma16816(Ors, pl, onesfrag, Ors);

#pragma unroll
            for (int dhb = 0; dhb < 4; ++dhb) {
                uint32_t m0r, m1r, m2r, m3r;
                ldsm_x4(m0r, m1r, m2r, m3r,
                        bufb + v_hl + v_laneoff + (uint32_t)dhb * 1152u + (uint32_t)j * 32u);
                uint32_t bh2[2] = {m0r, m1r}, bl2[2] = {m2r, m3r};
                mma16816(O[dhb], ph, bh2, O[dhb]);
                mma16816(O[dhb], ph, bl2, O[dhb]);
                mma16816(O[dhb], pl, bh2, O[dhb]);
            }
        }
        __syncthreads();
    }

    float inv0 = 1.f / Ors[0];
    float inv1 = 1.f / Ors[2];

    const size_t rowbase = (size_t)b * HW * (DIMC / 2);
    const uint32_t colw = (uint32_t)(h * 32) / 2 + (uint32_t)(c2);
#pragma unroll
    for (int dhb = 0; dhb < 4; ++dhb) {
        float a0 = O[dhb][0] * inv0, a1 = O[dhb][1] * inv0;
        float a2 = O[dhb][2] * inv1, a3 = O[dhb][3] * inv1;
        uint32_t h0 = pack_bf16(a0, a1);
        uint32_t l0 = pack_bf16(a0 - __uint_as_float(h0 << 16),
                                a1 - __uint_as_float(h0 & 0xffff0000u));
        uint32_t h1 = pack_bf16(a2, a3);
        uint32_t l1 = pack_bf16(a2 - __uint_as_float(h1 << 16),
                                a3 - __uint_as_float(h1 & 0xffff0000u));
        size_t i0 = rowbase + (size_t)(m0 + mrow + r) * 128 + colw + dhb * 4;
        size_t i1 = rowbase + (size_t)(m0 + mrow + r + 8) * 128 + colw + dhb * 4;
        aothi[i0] = h0; aotlo[i0] = l0;
        aothi[i1] = h1; aotlo[i1] = l1;
    }
}

// ==================== launch ====================
extern "C" void kernel_launch(void* const* d_in, const int* in_sizes, int n_in,
                              void* d_out, int out_size)
{
    (void)in_sizes; (void)n_in; (void)out_size;
    const float* x    = (const float*)d_in[0];
    const float* kv   = (const float*)d_in[1];
    const float* wq   = (const float*)d_in[2];
    const float* bq   = (const float*)d_in[3];
    const float* wk   = (const float*)d_in[4];
    const float* bk   = (const float*)d_in[5];
    const float* wv   = (const float*)d_in[6];
    const float* bv   = (const float*)d_in[7];
    const float* wdw  = (const float*)d_in[8];
    const float* bdw  = (const float*)d_in[9];
    const float* lnw  = (const float*)d_in[10];
    const float* lnb  = (const float*)d_in[11];
    const float* woff = (const float*)d_in[12];
    const float* wo   = (const float*)d_in[13];
    const float* bo   = (const float*)d_in[14];
    float* out = (float*)d_out;

    float *q, *kvT;
    __nv_bfloat16 *kvshi, *kvslo, *kthi, *ktlo, *vhi, *vlo;
    __nv_bfloat16 *wqhi, *wqlo, *wohi, *wolo, *wkhi, *wklo, *wvhi, *wvlo;
    __nv_bfloat16 *xthi, *xtlo, *aothi, *aotlo;
    cudaGetSymbolAddress((void**)&q,     g_q);
    cudaGetSymbolAddress((void**)&kvT,   g_kvT);
    cudaGetSymbolAddress((void**)&kvshi, g_kvshi);
    cudaGetSymbolAddress((void**)&kvslo, g_kvslo);
    cudaGetSymbolAddress((void**)&kthi,  g_kthi);
    cudaGetSymbolAddress((void**)&ktlo,  g_ktlo);
    cudaGetSymbolAddress((void**)&vhi,   g_vhi);
    cudaGetSymbolAddress((void**)&vlo,   g_vlo);
    cudaGetSymbolAddress((void**)&wqhi,  g_wqhi);
    cudaGetSymbolAddress((void**)&wqlo,  g_wqlo);
    cudaGetSymbolAddress((void**)&wohi,  g_wohi);
    cudaGetSymbolAddress((void**)&wolo,  g_wolo);
    cudaGetSymbolAddress((void**)&wkhi,  g_wkhi);
    cudaGetSymbolAddress((void**)&wklo,  g_wklo);
    cudaGetSymbolAddress((void**)&wvhi,  g_wvhi);
    cudaGetSymbolAddress((void**)&wvlo,  g_wvlo);
    cudaGetSymbolAddress((void**)&xthi,  g_xthi);
    cudaGetSymbolAddress((void**)&xtlo,  g_xtlo);
    cudaGetSymbolAddress((void**)&aothi, g_aothi);
    cudaGetSymbolAddress((void**)&aotlo, g_aotlo);

    cudaFuncSetAttribute(attn_mma_kernel,    cudaFuncAttributeMaxDynamicSharedMemorySize, A_SMEM);
    cudaFuncSetAttribute(gemm_tc_kernel,     cudaFuncAttributeMaxDynamicSharedMemorySize, G_SMEM);
    cudaFuncSetAttribute(gemm_kv_tc_kernel,  cudaFuncAttributeMaxDynamicSharedMemorySize, G_SMEM);
    cudaFuncSetAttribute(offset_sample_kernel, cudaFuncAttributeMaxDynamicSharedMemorySize, OS_SMEM);

    preproc_kernel<<<10240, 256>>>(wq, wo, wk, wv, x, kv,
                                   wqhi, wqlo, wohi, wolo, wkhi, wklo, wvhi, wvlo,
                                   xthi, xtlo, kvT);
    gemm_tc_kernel<<<dim3(HW / 64, 2, BATCH), 256, G_SMEM>>>(
        (const uint32_t*)wqhi, (const uint32_t*)wqlo, bq,
        (const uint32_t*)xthi, (const uint32_t*)xtlo, q);
    offset_sample_kernel<<<dim3(6, 64), 256, OS_SMEM>>>(q, kvT, wdw, bdw, lnw, lnb, woff,
                                                        kvshi, kvslo);
    gemm_kv_tc_kernel<<<dim3(NKS / 64, 4, BATCH), 256, G_SMEM>>>(
        (const uint32_t*)wkhi, (const uint32_t*)wklo,
        (const uint32_t*)wvhi, (const uint32_t*)wvlo, bk, bv,
        (const uint32_t*)kvshi, (const uint32_t*)kvslo,
        kthi, ktlo, (uint32_t*)vhi, (uint32_t*)vlo);
    attn_mma_kernel<<<dim3(HW / 128, 64), 256, A_SMEM>>>(
        q, (const uint32_t*)kthi, (const uint32_t*)ktlo,
        (const uint32_t*)vhi, (const uint32_t*)vlo,
        (uint32_t*)aothi, (uint32_t*)aotlo);
    gemm_tc_kernel<<<dim3(HW / 64, 2, BATCH), 256, G_SMEM>>>(
        (const uint32_t*)wohi, (const uint32_t*)wolo, bo,
        (const uint32_t*)aothi, (const uint32_t*)aotlo, out);
}

// round 17
// speedup vs baseline: 1.0570x; 1.0570x over previous
#include <cuda_runtime.h>
#include <cuda_bf16.h>
#include <math.h>
#include <stdint.h>

#define BATCH 8
#define DIMC  256
#define HH    48
#define WWD   48
#define HW    2304
#define HEADS 8
#define DH    32
#define HKD   24
#define NKS   576
#define ATTN_SCALE 0.17677669529663687f
#define ATTN_SCALE_LOG2E 0.25501633617699413f   // ATTN_SCALE / ln(2)

// ==================== scratch (device globals) ====================
__device__ float g_q   [BATCH * DIMC * HW];
__device__ float g_kvT [64 * HW * DH];
__device__ __nv_bfloat16 g_kvshi[BATCH * NKS * DIMC];
__device__ __nv_bfloat16 g_kvslo[BATCH * NKS * DIMC];
__device__ __nv_bfloat16 g_kthi[64 * NKS * DH];
__device__ __nv_bfloat16 g_ktlo[64 * NKS * DH];
__device__ __nv_bfloat16 g_vhi [64 * DH * NKS];
__device__ __nv_bfloat16 g_vlo [64 * DH * NKS];
__device__ __nv_bfloat16 g_wqhi[DIMC * DIMC], g_wqlo[DIMC * DIMC];
__device__ __nv_bfloat16 g_wohi[DIMC * DIMC], g_wolo[DIMC * DIMC];
__device__ __nv_bfloat16 g_wkhi[DIMC * DIMC], g_wklo[DIMC * DIMC];
__device__ __nv_bfloat16 g_wvhi[DIMC * DIMC], g_wvlo[DIMC * DIMC];
__device__ __nv_bfloat16 g_xthi[BATCH * HW * DIMC], g_xtlo[BATCH * HW * DIMC];
__device__ __nv_bfloat16 g_aothi[BATCH * HW * DIMC], g_aotlo[BATCH * HW * DIMC];

// ==================== helpers ====================
__device__ __forceinline__ float warp_sum(float v) {
#pragma unroll
    for (int o = 16; o; o >>= 1) v += __shfl_xor_sync(0xffffffffu, v, o);
    return v;
}
__device__ __forceinline__ uint32_t smem_u32(const void* p) {
    uint32_t a;
    asm("{ .reg .u64 t; cvta.to.shared.u64 t, %1; cvt.u32.u64 %0, t; }" : "=r"(a) : "l"(p));
    return a;
}
__device__ __forceinline__ uint32_t pack_bf16(float a, float b) {
    uint32_t r;
    asm("cvt.rn.satfinite.bf16x2.f32 %0, %1, %2;" : "=r"(r) : "f"(b), "f"(a));
    return r;
}
__device__ __forceinline__ float ex2f(float x) {
    float r;
    asm("ex2.approx.f32 %0, %1;" : "=f"(r) : "f"(x));
    return r;
}
__device__ __forceinline__ void mma16816(float* d, const uint32_t* a, const uint32_t* b,
                                         const float* c) {
    asm volatile("mma.sync.aligned.m16n8k16.row.col.f32.bf16.bf16.f32 "
        "{%0,%1,%2,%3}, {%4,%5,%6,%7}, {%8,%9}, {%10,%11,%12,%13};"
        : "=f"(d[0]), "=f"(d[1]), "=f"(d[2]), "=f"(d[3])
        : "r"(a[0]), "r"(a[1]), "r"(a[2]), "r"(a[3]),
          "r"(b[0]), "r"(b[1]),
          "f"(c[0]), "f"(c[1]), "f"(c[2]), "f"(c[3]));
}
__device__ __forceinline__ void ldsm_x4(uint32_t& r0, uint32_t& r1, uint32_t& r2,
                                        uint32_t& r3, uint32_t addr) {
    asm volatile("ldmatrix.sync.aligned.m8n8.x4.shared.b16 {%0,%1,%2,%3}, [%4];"
                 : "=r"(r0), "=r"(r1), "=r"(r2), "=r"(r3) : "r"(addr));
}
__device__ __forceinline__ void ldsm_x2(uint32_t& r0, uint32_t& r1, uint32_t addr) {
    asm volatile("ldmatrix.sync.aligned.m8n8.x2.shared.b16 {%0,%1}, [%2];"
                 : "=r"(r0), "=r"(r1) : "r"(addr));
}
__device__ __forceinline__ void cp16(uint32_t saddr, const void* g) {
    asm volatile("cp.async.cg.shared.global [%0], [%1], 16;" :: "r"(saddr), "l"(g));
}
#define CP_COMMIT() asm volatile("cp.async.commit_group;" ::: "memory")
#define CP_WAIT2()  asm volatile("cp.async.wait_group 2;" ::: "memory")
#define CP_WAIT1()  asm volatile("cp.async.wait_group 1;" ::: "memory")
#define CP_WAIT0()  asm volatile("cp.async.wait_group 0;" ::: "memory")

// ==================== fused preprocessing ====================
__global__ void preproc_kernel(const float* __restrict__ wq, const float* __restrict__ wo,
                               const float* __restrict__ wk, const float* __restrict__ wv,
                               const float* __restrict__ x,  const float* __restrict__ kv,
                               __nv_bfloat16* __restrict__ wqhi, __nv_bfloat16* __restrict__ wqlo,
                               __nv_bfloat16* __restrict__ wohi, __nv_bfloat16* __restrict__ wolo,
                               __nv_bfloat16* __restrict__ wkhi, __nv_bfloat16* __restrict__ wklo,
                               __nv_bfloat16* __restrict__ wvhi, __nv_bfloat16* __restrict__ wvlo,
                               __nv_bfloat16* __restrict__ xthi, __nv_bfloat16* __restrict__ xtlo,
                               float* __restrict__ kvT)
{
    __shared__ float tile[32][33];
    const int blk = blockIdx.x;
    const int tid = threadIdx.x;

    if (blk < 1024) {
        int i = blk * 256 + tid;
        int which = i >> 16, j = i & 65535;
        const float* src = (which == 0) ? wq : (which == 1) ? wo : (which == 2) ? wk : wv;
        __nv_bfloat16* dhi = (which == 0) ? wqhi : (which == 1) ? wohi : (which == 2) ? wkhi : wvhi;
        __nv_bfloat16* dlo = (which == 0) ? wqlo : (which == 1) ? wolo : (which == 2) ? wklo : wvlo;
        float v = src[j];
        __nv_bfloat16 hi = __float2bfloat16(v);
        dhi[j] = hi;
        dlo[j] = __float2bfloat16(v - __bfloat162float(hi));
    } else if (blk < 5632) {
        int j = blk - 1024;
        int n0 = (j % 72) * 32, c0 = ((j / 72) & 7) * 32, b = j / 576;
        for (int i = tid; i < 1024; i += 256) {
            int c = i >> 5, n = i & 31;
            tile[c][n] = x[((size_t)b * DIMC + c0 + c) * HW + n0 + n];
        }
        __syncthreads();
        for (int i = tid; i < 1024; i += 256) {
            int n = i >> 5, c = i & 31;
            float v = tile[c][n];
            __nv_bfloat16 hi = __float2bfloat16(v);
            size_t idx = ((size_t)b * HW + n0 + n) * DIMC + c0 + c;
            xthi[idx] = hi;
            xtlo[idx] = __float2bfloat16(v - __bfloat162float(hi));
        }
    } else {
        int j = blk - 5632;
        int n0 = (j % 72) * 32, h = (j / 72) & 7, b = j / 576;
        for (int i = tid; i < 1024; i += 256) {
            int c = i >> 5, n = i & 31;
            tile[c][n] = kv[((size_t)b * DIMC + h * DH + c) * HW + n0 + n];
        }
        __syncthreads();
        for (int i = tid; i < 1024; i += 256) {
            int n = i >> 5, c = i & 31;
            kvT[(((size_t)(b * 8 + h)) * HW + n0 + n) * DH + c] = tile[c][n];
        }
    }
}

// ==================== TC mainloop (3-stage pipeline, per-ks B frags) ====================
#define G_BUF  30720
#define G_SMEM (3 * G_BUF)

__device__ __forceinline__ void tc_mainloop(
    uint32_t sb, int tid, int lane, int warp,
    const uint32_t* __restrict__ whi, const uint32_t* __restrict__ wlo, int m0,
    const uint32_t* __restrict__ xh,  const uint32_t* __restrict__ xl,  int n0,
    float acc[2][4][4])
{
    auto prefetch = [&](int kc, int buf) {
        const uint32_t bb = sb + buf * G_BUF;
#pragma unroll
        for (int s = tid; s < 1536; s += 256) {
            if (s < 512) {
                int row = s >> 2, p = s & 3;
                cp16(bb + row * 80 + p * 16, whi + (size_t)(m0 + row) * 128 + kc * 16 + p * 4);
            } else if (s < 1024) {
                int t = s - 512, row = t >> 2, p = t & 3;
                cp16(bb + 10240 + row * 80 + p * 16, wlo + (size_t)(m0 + row) * 128 + kc * 16 + p * 4);
            } else if (s < 1280) {
                int t = s - 1024, row = t >> 2, p = t & 3;
                cp16(bb + 20480 + row * 80 + p * 16, xh + (size_t)(n0 + row) * 128 + kc * 16 + p * 4);
            } else {
                int t = s - 1280, row = t >> 2, p = t & 3;
                cp16(bb + 25600 + row * 80 + p * 16, xl + (size_t)(n0 + row) * 128 + kc * 16 + p * 4);
            }
        }
        CP_COMMIT();
    };

    prefetch(0, 0);
    prefetch(1, 1);

    const int warp_m = warp >> 1, warp_n = warp & 1;
    const int m_base = warp_m * 32, n_base = warp_n * 32;
    const uint32_t a_laneoff  = (uint32_t)((lane & 15) * 80 + (lane >> 4) * 16);
    const uint32_t b2_laneoff = (uint32_t)((lane & 7) * 80 + ((lane >> 3) & 1) * 16);

    int buf = 0;
    for (int kc = 0; kc < 8; ++kc) {
        if (kc < 6)       { prefetch(kc + 2, (kc + 2) % 3); CP_WAIT2(); }
        else if (kc == 6) { CP_WAIT1(); }
        else              { CP_WAIT0(); }
        __syncthreads();
        const uint32_t bb = sb + buf * G_BUF;
        buf = (buf + 1) % 3;

#pragma unroll
        for (int ks = 0; ks < 2; ++ks) {
            uint32_t bfh[4][2], bfl[4][2];
#pragma unroll
            for (int nf = 0; nf < 4; ++nf) {
                uint32_t ad = bb + 20480u + (uint32_t)(n_base + nf * 8) * 80u +
                              b2_laneoff + (uint32_t)ks * 32u;
                ldsm_x2(bfh[nf][0], bfh[nf][1], ad);
                ldsm_x2(bfl[nf][0], bfl[nf][1], ad + 5120u);
            }
#pragma unroll
            for (int mf = 0; mf < 2; ++mf) {
                uint32_t ad = bb + (uint32_t)(m_base + mf * 16) * 80u + a_laneoff + (uint32_t)ks * 32u;
                uint32_t ah[4], al[4];
                ldsm_x4(ah[0], ah[1], ah[2], ah[3], ad);
                ldsm_x4(al[0], al[1], al[2], al[3], ad + 10240u);
#pragma unroll
                for (int nf = 0; nf < 4; ++nf) {
                    mma16816(acc[mf][nf], ah, bfh[nf], acc[mf][nf]);
                    mma16816(acc[mf][nf], ah, bfl[nf], acc[mf][nf]);
                    mma16816(acc[mf][nf], al, bfh[nf], acc[mf][nf]);
                }
            }
        }
        __syncthreads();
    }
}

// ---- q / o projection ----
__global__ void __launch_bounds__(256, 3)
gemm_tc_kernel(const uint32_t* __restrict__ whi, const uint32_t* __restrict__ wlo,
               const float* __restrict__ bias,
               const uint32_t* __restrict__ xthi, const uint32_t* __restrict__ xtlo,
               float* __restrict__ C)
{
    extern __shared__ char smem[];
    const uint32_t sb = smem_u32(smem);
    const int tid = threadIdx.x, lane = tid & 31, warp = tid >> 5;
    const int n0 = blockIdx.x * 64;
    const int m0 = blockIdx.y * 128;
    const int b  = blockIdx.z;

    float acc[2][4][4] = {};
    tc_mainloop(sb, tid, lane, warp, whi, wlo, m0,
                xthi + (size_t)b * HW * 128, xtlo + (size_t)b * HW * 128, n0, acc);

    const int warp_m = warp >> 1, warp_n = warp & 1;
    const int m_base = warp_m * 32, n_base = warp_n * 32;
    const int r = lane >> 2, c2 = lane & 3;
    float* Cb = C + (size_t)b * DIMC * HW;
#pragma unroll
    for (int mf = 0; mf < 2; ++mf) {
        int mrow = m0 + m_base + mf * 16;
        float b0 = bias[mrow + r], b1 = bias[mrow + r + 8];
#pragma unroll
        for (int nf = 0; nf < 4; ++nf) {
            int n = n0 + n_base + nf * 8 + c2 * 2;
            *(float2*)(Cb + (size_t)(mrow + r) * HW + n) =
                make_float2(acc[mf][nf][0] + b0, acc[mf][nf][1] + b0);
            *(float2*)(Cb + (size_t)(mrow + r + 8) * HW + n) =
                make_float2(acc[mf][nf][2] + b1, acc[mf][nf][3] + b1);
        }
    }
}

// ---- k / v projection ----
__global__ void __launch_bounds__(256, 3)
gemm_kv_tc_kernel(const uint32_t* __restrict__ wkhi, const uint32_t* __restrict__ wklo,
                  const uint32_t* __restrict__ wvhi, const uint32_t* __restrict__ wvlo,
                  const float* __restrict__ bk, const float* __restrict__ bv,
                  const uint32_t* __restrict__ kvshi, const uint32_t* __restrict__ kvslo,
                  __nv_bfloat16* __restrict__ kthi, __nv_bfloat16* __restrict__ ktlo,
                  uint32_t* __restrict__ vhi, uint32_t* __restrict__ vlo)
{
    extern __shared__ char smem[];
    const uint32_t sb = smem_u32(smem);
    const int tid = threadIdx.x, lane = tid & 31, warp = tid >> 5;
    const int n0 = blockIdx.x * 64;
    const bool isV = blockIdx.y >= 2;
    const int m0 = (blockIdx.y & 1) * 128;
    const int b  = blockIdx.z;
    const uint32_t* whi = isV ? wvhi : wkhi;
    const uint32_t* wlo = isV ? wvlo : wklo;
    const float* bias = isV ? bv : bk;

    float acc[2][4][4] = {};
    tc_mainloop(sb, tid, lane, warp, whi, wlo, m0,
                kvshi + (size_t)b * NKS * 128, kvslo + (size_t)b * NKS * 128, n0, acc);

    const int warp_m = warp >> 1, warp_n = warp & 1;
    const int m_base = warp_m * 32, n_base = warp_n * 32;
    const int r = lane >> 2, c2 = lane & 3;

#pragma unroll
    for (int mf = 0; mf < 2; ++mf) {
        const int mrow = m0 + m_base + mf * 16 + r;
        const int bh = b * 8 + (mrow >> 5);
        const int dh = mrow & 31;
        const float b0 = bias[mrow], b1 = bias[mrow + 8];
#pragma unroll
        for (int nf = 0; nf < 4; ++nf) {
            const int n = n0 + n_base + nf * 8 + c2 * 2;
            float a0 = acc[mf][nf][0] + b0, a1 = acc[mf][nf][1] + b0;
            float a2 = acc[mf][nf][2] + b1, a3 = acc[mf][nf][3] + b1;
            float h0 = __bfloat162float(__float2bfloat16(a0));
            float h1 = __bfloat162float(__float2bfloat16(a1));
            float h2 = __bfloat162float(__float2bfloat16(a2));
            float h3 = __bfloat162float(__float2bfloat16(a3));
            if (!isV) {
                __nv_bfloat16* oh = kthi + (size_t)bh * NKS * DH;
                __nv_bfloat16* ol = ktlo + (size_t)bh * NKS * DH;
                oh[(size_t)n * DH + dh]           = __float2bfloat16(h0);
                oh[(size_t)(n + 1) * DH + dh]     = __float2bfloat16(h1);
                oh[(size_t)n * DH + dh + 8]       = __float2bfloat16(h2);
                oh[(size_t)(n + 1) * DH + dh + 8] = __float2bfloat16(h3);
                ol[(size_t)n * DH + dh]           = __float2bfloat16(a0 - h0);
                ol[(size_t)(n + 1) * DH + dh]     = __float2bfloat16(a1 - h1);
                ol[(size_t)n * DH + dh + 8]       = __float2bfloat16(a2 - h2);
                ol[(size_t)(n + 1) * DH + dh + 8] = __float2bfloat16(a3 - h3);
            } else {
                uint32_t* oh = vhi + (size_t)bh * DH * (NKS / 2);
                uint32_t* ol = vlo + (size_t)bh * DH * (NKS / 2);
                oh[(size_t)dh * (NKS / 2) + n / 2]       = pack_bf16(h0, h1);
                oh[(size_t)(dh + 8) * (NKS / 2) + n / 2] = pack_bf16(h2, h3);
                ol[(size_t)dh * (NKS / 2) + n / 2]       = pack_bf16(a0 - h0, a1 - h1);
                ol[(size_t)(dh + 8) * (NKS / 2) + n / 2] = pack_bf16(a2 - h2, a3 - h3);
            }
        }
    }
}

// ==================== offset + sample -> split bf16 [pos][ch] ====================
#define OS_SMEM (528 * 33 * 4)

__global__ void __launch_bounds__(256)
offset_sample_kernel(const float* __restrict__ q,
                     const float* __restrict__ kvT,
                     const float* __restrict__ w_dw,
                     const float* __restrict__ b_dw,
                     const float* __restrict__ ln_w,
                     const float* __restrict__ ln_b,
                     const float* __restrict__ w_off,
                     __nv_bfloat16* __restrict__ kvshi,
                     __nv_bfloat16* __restrict__ kvslo)
{
    extern __shared__ float sp[];
    __shared__ float s_wdw[32 * 25];
    __shared__ float s_bdw[32], s_lnw[32], s_lnb[32], s_woff[64];

    const int tid = threadIdx.x;
    const int bh = blockIdx.y, b = bh >> 3, h = bh & 7;
    const int hk0 = blockIdx.x * 4;
    const int y0 = 2 * hk0 - 2;

    for (int i = tid; i < 800; i += 256) s_wdw[i] = w_dw[i];
    if (tid < 32) { s_bdw[tid] = b_dw[tid]; s_lnw[tid] = ln_w[tid]; s_lnb[tid] = ln_b[tid]; }
    if (tid < 64) s_woff[tid] = w_off[tid];

    const float* qh = q + (size_t)(b * DIMC + h * DH) * HW;
    for (int i = tid; i < 16896; i += 256) {
        int dh = i / 528, p = i - dh * 528;
        int y = y0 + p / 48, x = p - (p / 48) * 48;
        float v = 0.f;
        if ((unsigned)y < (unsigned)HH)
            v = qh[(size_t)dh * HW + y * WWD + x];
        sp[p * 33 + dh] = v;
    }
    __syncthreads();

    const int lane = tid & 31, warp = tid >> 5;
    const float* kvb = kvT + (size_t)bh * HW * DH;
    __nv_bfloat16* outh = kvshi + ((size_t)b * NKS) * DIMC + h * DH;
    __nv_bfloat16* outl = kvslo + ((size_t)b * NKS) * DIMC + h * DH;

#pragma unroll
    for (int s = 0; s < 12; ++s) {
        const int p = s * 8 + warp;
        const int hk = hk0 + p / 24;
        const int wk = p - (p / 24) * 24;
        const int pos = hk * HKD + wk;

        const int dy = 2 * (hk - hk0);
        float t = 0.f;
#pragma unroll
        for (int i = 0; i < 5; ++i) {
            const int rb = (dy + i) * 48;
#pragma unroll
            for (int j = 0; j < 5; ++j) {
                int xx = wk * 2 - 2 + j;
                if ((unsigned)xx < (unsigned)WWD)
                    t += sp[(rb + xx) * 33 + lane] * s_wdw[lane * 25 + i * 5 + j];
            }
        }
        t += s_bdw[lane];

        float mu  = warp_sum(t) * (1.f / 32.f);
        float d   = t - mu;
        float var = warp_sum(d * d) * (1.f / 32.f);
        t = d * rsqrtf(var + 1e-5f) * s_lnw[lane] + s_lnb[lane];
        t = 0.5f * t * (1.f + erff(t * 0.70710678118654752f));

        float o0 = warp_sum(s_woff[lane] * t);
        float o1 = warp_sum(s_woff[32 + lane] * t);

        const float refy = (0.5f + (float)hk) * (2.f / 23.f) - 1.f;
        const float refx = (0.5f + (float)wk) * (2.f / 23.f) - 1.f;
        float py = fminf(fmaxf(o0 + refy, -1.f), 1.f);
        float px = fminf(fmaxf(o1 + refx, -1.f), 1.f);

        float gx = (px + 1.f) * 0.5f * 47.f;
        float gy = (py + 1.f) * 0.5f * 47.f;
        float fx = floorf(gx), fy = floorf(gy);
        float wx = gx - fx,   wy = gy - fy;
        int x0i = min(max((int)fx, 0), 47);
        int x1i = min(max((int)fx + 1, 0), 47);
        int y0i = min(max((int)fy, 0), 47);
        int y1i = min(max((int)fy + 1, 0), 47);

        float v00 = kvb[(size_t)(y0i * WWD + x0i) * DH + lane];
        float v01 = kvb[(size_t)(y0i * WWD + x1i) * DH + lane];
        float v10 = kvb[(size_t)(y1i * WWD + x0i) * DH + lane];
        float v11 = kvb[(size_t)(y1i * WWD + x1i) * DH + lane];

        float val = (1.f - wx) * (1.f - wy) * v00 + wx * (1.f - wy) * v01 +
                    (1.f - wx) * wy * v10 + wx * wy * v11;

        __nv_bfloat16 hi = __float2bfloat16(val);
        outh[(size_t)pos * DIMC + lane] = hi;
        outl[(size_t)pos * DIMC + lane] = __float2bfloat16(val - __bfloat162float(hi));
    }
}

// ==================== streamed mma.sync attention (Qh only; QK 2-product) ====================
#define BUF_SZ  19456
#define A_SMEM  (2 * BUF_SZ)

__global__ void __launch_bounds__(256, 4)
attn_mma_kernel(const float* __restrict__ q,
                const uint32_t* __restrict__ kthi, const uint32_t* __restrict__ ktlo,
                const uint32_t* __restrict__ vhi,  const uint32_t* __restrict__ vlo,
                uint32_t* __restrict__ aothi, uint32_t* __restrict__ aotlo)
{
    extern __shared__ char smem[];
    const uint32_t sb = smem_u32(smem);
    __nv_bfloat16* sqh = (__nv_bfloat16*)(smem + BUF_SZ);   // [128][36], in buffer 1

    const int tid  = threadIdx.x;
    const int lane = tid & 31, warp = tid >> 5;
    const int bh = blockIdx.y, b = bh >> 3, h = bh & 7;
    const int m0 = blockIdx.x * 128;

    const uint32_t* gkh = kthi + (size_t)bh * 9216;
    const uint32_t* gkl = ktlo + (size_t)bh * 9216;
    const uint32_t* gvh = vhi + (size_t)bh * 9216;
    const uint32_t* gvl = vlo + (size_t)bh * 9216;

    auto prefetch = [&](int c, int buf) {
        const uint32_t bb = sb + buf * BUF_SZ;
#pragma unroll
        for (int s = tid; s < 1024; s += 256) {
            if (s < 256) {
                int n = s >> 2, p = s & 3;
                cp16(bb + n * 80 + p * 16, gkh + c * 1024 + s * 4);
            } else if (s < 512) {
                int t = s - 256, n = t >> 2, p = t & 3;
                cp16(bb + 5120 + n * 80 + p * 16, gkl + c * 1024 + t * 4);
            } else if (s < 768) {
                int t = s - 512, dh = t >> 3, p = t & 7;
                cp16(bb + 10240 + dh * 144 + p * 16, gvh + dh * 288 + c * 32 + p * 4);
            } else {
                int t = s - 768, dh = t >> 3, p = t & 7;
                cp16(bb + 14848 + dh * 144 + p * 16, gvl + dh * 288 + c * 32 + p * 4);
            }
        }
        CP_COMMIT();
    };

    prefetch(0, 0);

    // stage Q (hi only): error from dropping Ql*K is ~1e-4 on logits (threshold 1e-3)
    const float* qb = q + (size_t)(b * DIMC + h * DH) * HW + m0;
    for (int i = tid; i < 4096; i += 256) {
        int dh = i >> 7, m = i & 127;
        float x = qb[(size_t)dh * HW + m] * ATTN_SCALE_LOG2E;
        sqh[m * 36 + dh] = __float2bfloat16(x);
    }
    __syncthreads();

    const int r = lane >> 2, c2 = lane & 3;
    const int mrow = warp * 16;
    uint32_t qfh[2][4];
#pragma unroll
    for (int ks = 0; ks < 2; ++ks) {
        int k0 = ks * 16 + c2 * 2;
        qfh[ks][0] = *(const uint32_t*)(sqh + (mrow + r) * 36 + k0);
        qfh[ks][1] = *(const uint32_t*)(sqh + (mrow + r + 8) * 36 + k0);
        qfh[ks][2] = *(const uint32_t*)(sqh + (mrow + r) * 36 + k0 + 8);
        qfh[ks][3] = *(const uint32_t*)(sqh + (mrow + r + 8) * 36 + k0 + 8);
    }
    __syncthreads();

    const uint32_t k_laneoff = ((uint32_t)(lane & 7) * 20u + (uint32_t)(lane >> 3) * 4u) * 4u;
    const uint32_t v_laneoff = ((uint32_t)(lane & 7) * 36u + (uint32_t)((lane >> 3) & 1) * 4u) * 4u;
    const uint32_t v_hl = (lane < 16) ? 10240u : 14848u;

    float O[4][4] = {};
    float rs0 = 0.f, rs1 = 0.f;

    for (int chunk = 0; chunk < 9; ++chunk) {
        if (chunk < 8) { prefetch(chunk + 1, (chunk + 1) & 1); CP_WAIT1(); }
        else           { CP_WAIT0(); }
        __syncthreads();

        const uint32_t bufb = sb + (chunk & 1) * BUF_SZ;
        float S[8][4];
#pragma unroll
        for (int nb = 0; nb < 8; ++nb)
#pragma unroll
            for (int i = 0; i < 4; ++i) S[nb][i] = 0.f;

        // S = Qh*(Kh + Kl)  (2-product emulation; Ql dropped)
#pragma unroll
        for (int nb = 0; nb < 8; ++nb) {
            uint32_t h0, h1, h2, h3, l0, l1, l2, l3;
            ldsm_x4(h0, h1, h2, h3, bufb + k_laneoff + (uint32_t)nb * 640u);
            ldsm_x4(l0, l1, l2, l3, bufb + 5120u + k_laneoff + (uint32_t)nb * 640u);
            uint32_t bh0[2] = {h0, h1}, bh1[2] = {h2, h3};
            uint32_t bl0[2] = {l0, l1}, bl1[2] = {l2, l3};
            mma16816(S[nb], qfh[0], bh0, S[nb]);
            mma16816(S[nb], qfh[1], bh1, S[nb]);
            mma16816(S[nb], qfh[0], bl0, S[nb]);
            mma16816(S[nb], qfh[1], bl1, S[nb]);
        }

#pragma unroll
        for (int j = 0; j < 4; ++j) {
            float e[8];
#pragma unroll
            for (int i = 0; i < 4; ++i) {
                e[i]     = ex2f(S[2 * j][i]);
                e[4 + i] = ex2f(S[2 * j + 1][i]);
            }
            rs0 += e[0] + e[1] + e[4] + e[5];
            rs1 += e[2] + e[3] + e[6] + e[7];

            uint32_t ph[4], pl[4];
#pragma unroll
            for (int i = 0; i < 4; ++i) {
                float a = e[2 * i], bb2 = e[2 * i + 1];
                uint32_t hp = pack_bf16(a, bb2);
                float ra = a   - __uint_as_float(hp << 16);
                float rb = bb2 - __uint_as_float(hp & 0xffff0000u);
                ph[i] = hp;
                pl[i] = pack_bf16(ra, rb);
            }

#pragma unroll
            for (int dhb = 0; dhb < 4; ++dhb) {
                uint32_t m0r, m1r, m2r, m3r;
                ldsm_x4(m0r, m1r, m2r, m3r,
                        bufb + v_hl + v_laneoff + (uint32_t)dhb * 1152u + (uint32_t)j * 32u);
                uint32_t bh2[2] = {m0r, m1r}, bl2[2] = {m2r, m3r};
                mma16816(O[dhb], ph, bh2, O[dhb]);
                mma16816(O[dhb], ph, bl2, O[dhb]);
                mma16816(O[dhb], pl, bh2, O[dhb]);
            }
        }
        __syncthreads();
    }

    rs0 += __shfl_xor_sync(0xffffffffu, rs0, 1);
    rs0 += __shfl_xor_sync(0xffffffffu, rs0, 2);
    rs1 += __shfl_xor_sync(0xffffffffu, rs1, 1);
    rs1 += __shfl_xor_sync(0xffffffffu, rs1, 2);
    float inv0 = 1.f / rs0, inv1 = 1.f / rs1;

    const size_t rowbase = (size_t)b * HW * (DIMC / 2);
    const uint32_t colw = (uint32_t)(h * 32) / 2 + (uint32_t)(c2);
#pragma unroll
    for (int dhb = 0; dhb < 4; ++dhb) {
        float a0 = O[dhb][0] * inv0, a1 = O[dhb][1] * inv0;
        float a2 = O[dhb][2] * inv1, a3 = O[dhb][3] * inv1;
        uint32_t h0 = pack_bf16(a0, a1);
        uint32_t l0 = pack_bf16(a0 - __uint_as_float(h0 << 16),
                                a1 - __uint_as_float(h0 & 0xffff0000u));
        uint32_t h1 = pack_bf16(a2, a3);
        uint32_t l1 = pack_bf16(a2 - __uint_as_float(h1 << 16),
                                a3 - __uint_as_float(h1 & 0xffff0000u));
        size_t i0 = rowbase + (size_t)(m0 + mrow + r) * 128 + colw + dhb * 4;
        size_t i1 = rowbase + (size_t)(m0 + mrow + r + 8) * 128 + colw + dhb * 4;
        aothi[i0] = h0; aotlo[i0] = l0;
        aothi[i1] = h1; aotlo[i1] = l1;
    }
}

// ==================== launch ====================
extern "C" void kernel_launch(void* const* d_in, const int* in_sizes, int n_in,
                              void* d_out, int out_size)
{
    (void)in_sizes; (void)n_in; (void)out_size;
    const float* x    = (const float*)d_in[0];
    const float* kv   = (const float*)d_in[1];
    const float* wq   = (const float*)d_in[2];
    const float* bq   = (const float*)d_in[3];
    const float* wk   = (const float*)d_in[4];
    const float* bk   = (const float*)d_in[5];
    const float* wv   = (const float*)d_in[6];
    const float* bv   = (const float*)d_in[7];
    const float* wdw  = (const float*)d_in[8];
    const float* bdw  = (const float*)d_in[9];
    const float* lnw  = (const float*)d_in[10];
    const float* lnb  = (const float*)d_in[11];
    const float* woff = (const float*)d_in[12];
    const float* wo   = (const float*)d_in[13];
    const float* bo   = (const float*)d_in[14];
    float* out = (float*)d_out;

    float *q, *kvT;
    __nv_bfloat16 *kvshi, *kvslo, *kthi, *ktlo, *vhi, *vlo;
    __nv_bfloat16 *wqhi, *wqlo, *wohi, *wolo, *wkhi, *wklo, *wvhi, *wvlo;
    __nv_bfloat16 *xthi, *xtlo, *aothi, *aotlo;
    cudaGetSymbolAddress((void**)&q,     g_q);
    cudaGetSymbolAddress((void**)&kvT,   g_kvT);
    cudaGetSymbolAddress((void**)&kvshi, g_kvshi);
    cudaGetSymbolAddress((void**)&kvslo, g_kvslo);
    cudaGetSymbolAddress((void**)&kthi,  g_kthi);
    cudaGetSymbolAddress((void**)&ktlo,  g_ktlo);
    cudaGetSymbolAddress((void**)&vhi,   g_vhi);
    cudaGetSymbolAddress((void**)&vlo,   g_vlo);
    cudaGetSymbolAddress((void**)&wqhi,  g_wqhi);
    cudaGetSymbolAddress((void**)&wqlo,  g_wqlo);
    cudaGetSymbolAddress((void**)&wohi,  g_wohi);
    cudaGetSymbolAddress((void**)&wolo,  g_wolo);
    cudaGetSymbolAddress((void**)&wkhi,  g_wkhi);
    cudaGetSymbolAddress((void**)&wklo,  g_wklo);
    cudaGetSymbolAddress((void**)&wvhi,  g_wvhi);
    cudaGetSymbolAddress((void**)&wvlo,  g_wvlo);
    cudaGetSymbolAddress((void**)&xthi,  g_xthi);
    cudaGetSymbolAddress((void**)&xtlo,  g_xtlo);
    cudaGetSymbolAddress((void**)&aothi, g_aothi);
    cudaGetSymbolAddress((void**)&aotlo, g_aotlo);

    cudaFuncSetAttribute(attn_mma_kernel,    cudaFuncAttributeMaxDynamicSharedMemorySize, A_SMEM);
    cudaFuncSetAttribute(gemm_tc_kernel,     cudaFuncAttributeMaxDynamicSharedMemorySize, G_SMEM);
    cudaFuncSetAttribute(gemm_kv_tc_kernel,  cudaFuncAttributeMaxDynamicSharedMemorySize, G_SMEM);
    cudaFuncSetAttribute(offset_sample_kernel, cudaFuncAttributeMaxDynamicSharedMemorySize, OS_SMEM);

    preproc_kernel<<<10240, 256>>>(wq, wo, wk, wv, x, kv,
                                   wqhi, wqlo, wohi, wolo, wkhi, wklo, wvhi, wvlo,
                                   xthi, xtlo, kvT);
    gemm_tc_kernel<<<dim3(HW / 64, 2, BATCH), 256, G_SMEM>>>(
        (const uint32_t*)wqhi, (const uint32_t*)wqlo, bq,
        (const uint32_t*)xthi, (const uint32_t*)xtlo, q);
    offset_sample_kernel<<<dim3(6, 64), 256, OS_SMEM>>>(q, kvT, wdw, bdw, lnw, lnb, woff,
                                                        kvshi, kvslo);
    gemm_kv_tc_kernel<<<dim3(NKS / 64, 4, BATCH), 256, G_SMEM>>>(
        (const uint32_t*)wkhi, (const uint32_t*)wklo,
        (const uint32_t*)wvhi, (const uint32_t*)wvlo, bk, bv,
        (const uint32_t*)kvshi, (const uint32_t*)kvslo,
        kthi, ktlo, (uint32_t*)vhi, (uint32_t*)vlo);
    attn_mma_kernel<<<dim3(HW / 128, 64), 256, A_SMEM>>>(
        q, (const uint32_t*)kthi, (const uint32_t*)ktlo,
        (const uint32_t*)vhi, (const uint32_t*)vlo,
        (uint32_t*)aothi, (uint32_t*)aotlo);
    gemm_tc_kernel<<<dim3(HW / 64, 2, BATCH), 256, G_SMEM>>>(
        (const uint32_t*)wohi, (const uint32_t*)wolo, bo,
        (const uint32_t*)aothi, (const uint32_t*)aotlo, out);
}